// round 6
// baseline (speedup 1.0000x reference)
#include <cuda_runtime.h>
#include <stdint.h>
#include <math.h>

// ---------------- problem constants ----------------
#define CDIM   1024
#define NTOK   16384             // B*T = 4*4096
#define C3     (3 * CDIM)        // 3072

// ---------------- scratch (allocation-free rule) ----------------
__device__ float g_qkv[(size_t)NTOK * C3];
__device__ float g_y  [(size_t)NTOK * CDIM];
__device__ float g_xt [(size_t)NTOK * CDIM];
__device__ float g_w1t[(size_t)C3 * CDIM];
__device__ float g_w2t[(size_t)CDIM * CDIM];

// ---------------- PTX helpers (baseline sm_80+ only) ----------------
__device__ __forceinline__ uint32_t smem_u32(const void* p) {
    uint32_t a;
    asm("{ .reg .u64 t; cvta.to.shared.u64 t, %1; cvt.u32.u64 %0, t; }"
        : "=r"(a) : "l"(p));
    return a;
}

#define CP_ASYNC16(dst_u32, src_ptr) \
    asm volatile("cp.async.cg.shared.global [%0], [%1], 16;" \
                 :: "r"(dst_u32), "l"(src_ptr) : "memory")
#define CP_COMMIT() asm volatile("cp.async.commit_group;" ::: "memory")
#define CP_WAIT(n)  asm volatile("cp.async.wait_group %0;" :: "n"(n) : "memory")

#define LDSM4(r, addr) \
    asm volatile("ldmatrix.sync.aligned.m8n8.x4.shared.b16 {%0,%1,%2,%3}, [%4];" \
        : "=r"((r)[0]), "=r"((r)[1]), "=r"((r)[2]), "=r"((r)[3]) : "r"(addr))

#define MMA_TF32(d, a, b0, b1) \
    asm volatile("mma.sync.aligned.m16n8k8.row.col.f32.tf32.tf32.f32 " \
        "{%0,%1,%2,%3}, {%4,%5,%6,%7}, {%8,%9}, {%0,%1,%2,%3};" \
        : "+f"((d)[0]), "+f"((d)[1]), "+f"((d)[2]), "+f"((d)[3]) \
        : "r"((a)[0]), "r"((a)[1]), "r"((a)[2]), "r"((a)[3]), "r"(b0), "r"(b1))

__device__ __forceinline__ uint32_t f2tf32(float x) {
    uint32_t r;
    asm("cvt.rna.tf32.f32 %0, %1;" : "=r"(r) : "f"(x));
    return r;
}

// ---------------- smem geometry (XOR swizzle, pitch = 128 B exact) ----------------
#define PITCH    128
#define A_TILE_B (128 * PITCH)           // 16384
#define B_TILE_B (256 * PITCH)           // 32768
#define OFF_B    A_TILE_B
#define STAGE_B  (A_TILE_B + B_TILE_B)   // 49152
#define NSTG     4
#define SMEM_B   (NSTG * STAGE_B)        // 196608 B -> 1 CTA/SM
#define BKC      32                      // K per chunk (4 k8 steps)

// ---------------------------------------------------------------------------
// C[M,N] = A[M,K] @ B[N,K]^T (+bias); fp32 inputs already tf32-rounded.
// CTA tile 128x256, 8 warps (warp tile 64x64), 4-stage cp.async, TF32 HMMA.
// ---------------------------------------------------------------------------
__global__ __launch_bounds__(256) void tf32_gemm(
    const float* __restrict__ A, const float* __restrict__ B,
    const float* __restrict__ bias, float* __restrict__ C,
    int M, int N, int K)
{
    extern __shared__ char sm[];
    const uint32_t sbase = smem_u32(sm);

    const int tid  = threadIdx.x;
    const int lane = tid & 31;
    const int wid  = tid >> 5;
    const int wm   = wid & 1;       // M half (64 rows)
    const int wn   = wid >> 1;      // N quarter (64 cols)
    const int bm   = blockIdx.y * 128;
    const int bn   = blockIdx.x * 256;

    // ---- loader mapping ----
    const int lr = tid >> 1;            // 0..127
    const int lh = tid & 1;             // half-row selector
    const float* gA  = A + (size_t)(bm + lr) * K + lh * 16;
    const float* gB0 = B + (size_t)(bn + lr) * K + lh * 16;
    const float* gB1 = B + (size_t)(bn + 128 + lr) * K + lh * 16;
    uint32_t sw[4];
    #pragma unroll
    for (int j = 0; j < 4; j++) sw[j] = (uint32_t)(((lh * 4 + j) ^ (lr & 7)) << 4);
    const uint32_t sRowA  = (uint32_t)(lr * PITCH);
    const uint32_t sRowB0 = (uint32_t)(OFF_B + lr * PITCH);
    const uint32_t sRowB1 = (uint32_t)(OFF_B + (lr + 128) * PITCH);

    // ---- ldmatrix lane addressing (8 consecutive rows per tile: row&7 == lane&7) ----
    const int g  = lane >> 3;
    const int l8 = lane & 7;
    const int cA = g >> 1;
    const int cB = g & 1;
    const uint32_t aRow = (uint32_t)((wm * 64 + l8 + (g & 1) * 8) * PITCH);
    const uint32_t bRow = (uint32_t)((wn * 64 + l8 + (g >> 1) * 8) * PITCH);
    uint32_t aSw[4], bSw[4];
    #pragma unroll
    for (int s = 0; s < 4; s++) {
        aSw[s] = (uint32_t)(((s * 2 + cA) ^ l8) << 4);
        bSw[s] = (uint32_t)(((s * 2 + cB) ^ l8) << 4);
    }

    float acc[4][8][4];
    #pragma unroll
    for (int i = 0; i < 4; i++)
        #pragma unroll
        for (int j = 0; j < 8; j++)
            #pragma unroll
            for (int q = 0; q < 4; q++) acc[i][j][q] = 0.0f;

    const int KC = K / BKC;

    auto issue = [&](int stg, int ko) {
        const uint32_t d = sbase + (uint32_t)stg * STAGE_B;
        const float* sa  = gA  + ko;
        const float* sb0 = gB0 + ko;
        const float* sb1 = gB1 + ko;
        #pragma unroll
        for (int j = 0; j < 4; j++) {
            CP_ASYNC16(d + sRowA  + sw[j], sa  + j * 4);
            CP_ASYNC16(d + sRowB0 + sw[j], sb0 + j * 4);
            CP_ASYNC16(d + sRowB1 + sw[j], sb1 + j * 4);
        }
    };

    // prologue: 3 stages in flight
    issue(0, 0);       CP_COMMIT();
    issue(1, BKC);     CP_COMMIT();
    issue(2, 2 * BKC); CP_COMMIT();

    uint32_t af[2][4][4], bf[2][4][4];

    for (int c = 0; c < KC; c++) {
        const int rem = KC - 1 - c;
        if (rem >= 2)      { CP_WAIT(2); }
        else if (rem == 1) { CP_WAIT(1); }
        else               { CP_WAIT(0); }
        __syncthreads();
        if (c + 3 < KC) { issue((c + 3) % NSTG, (c + 3) * BKC); CP_COMMIT(); }

        const uint32_t stg = sbase + (uint32_t)(c % NSTG) * STAGE_B;
        const uint32_t aB  = stg + aRow;
        const uint32_t bB  = stg + OFF_B + bRow;

        // frags for k8-step 0
        #pragma unroll
        for (int i = 0; i < 4; i++) LDSM4(af[0][i], aB + aSw[0] + (uint32_t)(i * 16 * PITCH));
        #pragma unroll
        for (int p = 0; p < 4; p++) LDSM4(bf[0][p], bB + bSw[0] + (uint32_t)(p * 16 * PITCH));

        #pragma unroll
        for (int s = 0; s < 4; s++) {
            const int cur = s & 1;
            if (s < 3) {
                const int nxt = cur ^ 1;
                #pragma unroll
                for (int i = 0; i < 4; i++)
                    LDSM4(af[nxt][i], aB + aSw[s + 1] + (uint32_t)(i * 16 * PITCH));
                #pragma unroll
                for (int p = 0; p < 4; p++)
                    LDSM4(bf[nxt][p], bB + bSw[s + 1] + (uint32_t)(p * 16 * PITCH));
            }
            #pragma unroll
            for (int i = 0; i < 4; i++) {
                #pragma unroll
                for (int j = 0; j < 8; j++) {
                    const int p = j >> 1, q = j & 1;
                    MMA_TF32(acc[i][j], af[cur][i], bf[cur][p][q * 2], bf[cur][p][q * 2 + 1]);
                }
            }
        }
    }

    // ---- epilogue ----
    #pragma unroll
    for (int i = 0; i < 4; i++) {
        const int row = bm + wm * 64 + i * 16 + (lane >> 2);
        #pragma unroll
        for (int j = 0; j < 8; j++) {
            const int col = bn + wn * 64 + j * 8 + (lane & 3) * 2;
            float b0 = 0.f, b1 = 0.f;
            if (bias) { b0 = bias[col]; b1 = bias[col + 1]; }
            float2 v0 = make_float2(acc[i][j][0] + b0, acc[i][j][1] + b1);
            float2 v1 = make_float2(acc[i][j][2] + b0, acc[i][j][3] + b1);
            *(float2*)(C + (size_t)row * N + col)       = v0;
            *(float2*)(C + (size_t)(row + 8) * N + col) = v1;
        }
    }
}

// ---------------------------------------------------------------------------
__global__ __launch_bounds__(256) void round_tf32_kernel(
    const float* __restrict__ src, float* __restrict__ dst, int n4)
{
    const int i = blockIdx.x * blockDim.x + threadIdx.x;
    if (i >= n4) return;
    const float4 v = ((const float4*)src)[i];
    uint4 r;
    r.x = f2tf32(v.x); r.y = f2tf32(v.y);
    r.z = f2tf32(v.z); r.w = f2tf32(v.w);
    ((uint4*)dst)[i] = r;
}

// ---------------------------------------------------------------------------
// Per-token attention over heads (fp32), outputs tf32-rounded y.
// ---------------------------------------------------------------------------
__global__ __launch_bounds__(256) void attn_kernel(
    const float* __restrict__ qkv, float* __restrict__ y)
{
    __shared__ float sh[C3];
    __shared__ float att[16][16];

    const int token = blockIdx.x;
    const int tid   = threadIdx.x;
    const float* row = qkv + (size_t)token * C3;

    for (int i = tid; i < C3 / 4; i += 256)
        ((float4*)sh)[i] = ((const float4*)row)[i];
    __syncthreads();

    const int h = tid >> 4;
    const int gg = tid & 15;
    const float* qp = sh + h * 192;
    const float* kp = sh + gg * 192 + 64;

    float s = 0.0f;
    #pragma unroll
    for (int dd = 0; dd < 64; dd++) {
        int d = (dd + gg) & 63;
        s += qp[d] * kp[d];
    }
    att[h][gg] = s * 0.125f;
    __syncthreads();

    float m = -1e30f;
    #pragma unroll
    for (int j = 0; j < 16; j++) m = fmaxf(m, att[h][j]);
    float e = __expf(att[h][gg] - m);
    __syncthreads();
    att[h][gg] = e;
    __syncthreads();
    float denom = 0.0f;
    #pragma unroll
    for (int j = 0; j < 16; j++) denom += att[h][j];
    const float inv = 1.0f / denom;

    const int d0 = (tid & 15) * 4;
    float4 o = make_float4(0.f, 0.f, 0.f, 0.f);
    #pragma unroll
    for (int g2 = 0; g2 < 16; g2++) {
        const float w = att[h][g2];
        const float* vp = sh + g2 * 192 + 128 + d0;
        o.x += w * vp[0];
        o.y += w * vp[1];
        o.z += w * vp[2];
        o.w += w * vp[3];
    }
    uint4 r;
    r.x = f2tf32(o.x * inv);
    r.y = f2tf32(o.y * inv);
    r.z = f2tf32(o.z * inv);
    r.w = f2tf32(o.w * inv);
    *(uint4*)(y + (size_t)token * CDIM + h * 64 + d0) = r;
}

// ---------------------------------------------------------------------------
extern "C" void kernel_launch(void* const* d_in, const int* in_sizes, int n_in,
                              void* d_out, int out_size)
{
    const float* x    = (const float*)d_in[0];
    const float* Wqkv = (const float*)d_in[1];
    const float* Wout = (const float*)d_in[2];
    const float* bout = (const float*)d_in[3];
    float* out = (float*)d_out;

    float *qkv, *y, *xt, *w1t, *w2t;
    cudaGetSymbolAddress((void**)&qkv, g_qkv);
    cudaGetSymbolAddress((void**)&y,   g_y);
    cudaGetSymbolAddress((void**)&xt,  g_xt);
    cudaGetSymbolAddress((void**)&w1t, g_w1t);
    cudaGetSymbolAddress((void**)&w2t, g_w2t);

    cudaFuncSetAttribute(tf32_gemm, cudaFuncAttributeMaxDynamicSharedMemorySize, SMEM_B);

    // tf32 rounding passes (rna)
    round_tf32_kernel<<<(NTOK * CDIM / 4 + 255) / 256, 256>>>(x, xt, NTOK * CDIM / 4);
    round_tf32_kernel<<<(C3 * CDIM / 4 + 255) / 256, 256>>>(Wqkv, w1t, C3 * CDIM / 4);
    round_tf32_kernel<<<(CDIM * CDIM / 4 + 255) / 256, 256>>>(Wout, w2t, CDIM * CDIM / 4);

    // GEMM1: qkv = xt @ w1t^T   (16384 x 3072, K=1024)
    tf32_gemm<<<dim3(C3 / 256, NTOK / 128), 256, SMEM_B>>>(
        xt, w1t, nullptr, qkv, NTOK, C3, CDIM);

    // attention over heads (emits tf32-rounded y)
    attn_kernel<<<NTOK, 256>>>(qkv, y);

    // GEMM2: out = y @ w2t^T + bout   (16384 x 1024, K=1024)
    tf32_gemm<<<dim3(CDIM / 256, NTOK / 128), 256, SMEM_B>>>(
        y, w2t, bout, out, NTOK, CDIM, CDIM);
}